// round 15
// baseline (speedup 1.0000x reference)
#include <cuda_runtime.h>
#include <cuda_bf16.h>
#include <cstdint>

// Problem constants (fixed by setup_inputs)
#define NN    200000
#define D_IN  128
#define HID   256
#define OUTD  128
#define BATCH 2048
#define KF    16
#define N2    (BATCH*KF + BATCH)   // 34816
#define E1    (BATCH*KF)           // 32768

// Scratch (device globals; no runtime allocation allowed)
__device__ float g_h1s[BATCH * HID];        // [2048, 256] self rows of h1
__device__ float g_agg1[BATCH * HID];       // [2048, 256] segment sums of h1
__device__ float g_W1[HID * 2 * D_IN];      // [256, 256] = [W1n | W1h] (tf32-rounded)
__device__ float g_b1[HID];
__device__ float g_W2[OUTD * 2 * HID];      // [128, 512] = [W2n | W2h] (tf32-rounded)
__device__ float g_b2[OUTD];

__device__ __forceinline__ float to_tf32(float f) {
    uint32_t u;
    asm("cvt.rna.tf32.f32 %0, %1;" : "=r"(u) : "f"(f));
    return __uint_as_float(u);
}

#define MMA_TF32(d, a, b)                                                     \
    asm volatile(                                                             \
        "mma.sync.aligned.m16n8k8.row.col.f32.tf32.tf32.f32 "                 \
        "{%0,%1,%2,%3}, {%4,%5,%6,%7}, {%8,%9}, {%0,%1,%2,%3};"               \
        : "+f"((d)[0]), "+f"((d)[1]), "+f"((d)[2]), "+f"((d)[3])              \
        : "r"((a)[0]), "r"((a)[1]), "r"((a)[2]), "r"((a)[3]),                 \
          "r"((b)[0]), "r"((b)[1]))

__device__ __forceinline__ void cp_async16(void* smem_ptr, const void* gptr) {
    uint32_t sa = (uint32_t)__cvta_generic_to_shared(smem_ptr);
    asm volatile("cp.async.cg.shared.global [%0], [%1], 16;" :: "r"(sa), "l"(gptr) : "memory");
}

// ---------------------------------------------------------------------------
// Weight prep: grid=256, block=512.
// ---------------------------------------------------------------------------
__global__ void prep_w(const float* __restrict__ W1n, const float* __restrict__ b1n,
                       const float* __restrict__ W1h, const float* __restrict__ b1h,
                       const float* __restrict__ W2n, const float* __restrict__ b2n,
                       const float* __restrict__ W2h, const float* __restrict__ b2h) {
    int b = blockIdx.x;
    int k = threadIdx.x;
    if (k < 256) {
        float w = (k < D_IN) ? W1n[b * D_IN + k] : W1h[b * D_IN + (k - D_IN)];
        g_W1[b * 256 + k] = to_tf32(w);
        if (k == 0) g_b1[b] = b1n[b] + b1h[b];
    }
    if (b < OUTD) {
        float w = (k < HID) ? W2n[b * HID + k] : W2h[b * HID + (k - HID)];
        g_W2[b * 512 + k] = to_tf32(w);
        if (k == 0) g_b2[b] = b2n[b] + b2h[b];
    }
}

// ---------------------------------------------------------------------------
// Kernel 2: FUSED gather + tf32 GEMM + relu + segment-reduce.
//   A[i] = [ sum_j x[nbr2[i*16+j]] | x[nodes2[i]]*decay(i) ]  built on the fly
//   h1 = relu(A @ W1^T + b1); neighbor rows -> 16-row segment sums -> g_agg1;
//   self rows -> g_h1s.
// BM=64, BN=256 (A produced once), BK=32, 8 chunks. 8 warps, warp tile 32x64.
// As double-buffered [2][64][36] (STS by gather threads); Ws double-buffered
// [2][256][36] via cp.async. One __syncthreads per chunk.
// ---------------------------------------------------------------------------
#define AS1_F (64 * 36)       // 2304 floats per stage
#define WS1_F (256 * 36)      // 9216 floats per stage

__global__ __launch_bounds__(256, 2) void gemm1_fused(
        const float* __restrict__ x,
        const int*   __restrict__ nodes2,
        const int*   __restrict__ nbr2,
        const float* __restrict__ t2,
        const float* __restrict__ n_times2,
        const float* __restrict__ t_kernel,
        const float* __restrict__ W,
        const float* __restrict__ bias,
        float* __restrict__ Cself,
        float* __restrict__ Agg) {
    extern __shared__ float sm[];
    float* As = sm;                  // [2][64][36]
    float* Ws = sm + 2 * AS1_F;      // [2][256][36]

    const int tid  = threadIdx.x;
    const int lane = tid & 31;
    const int warp = tid >> 5;
    const int gid  = lane >> 2;      // 0..7
    const int tig  = lane & 3;       // 0..3
    const int wm   = (warp >> 2) << 5;   // 0 / 32
    const int wn   = (warp & 3) << 6;    // 0,64,128,192
    const long bm  = (long)blockIdx.x * 64;

    // gather mapping: 4 threads per row, each owns 8 cols (2 float4)
    const int  grow   = tid >> 2;            // 0..63
    const int  gq     = tid & 3;             // col quad
    const long grow_g = bm + grow;

    // per-thread 4 of the row's 16 neighbor indices
    int4 nb4 = *(const int4*)(nbr2 + grow_g * KF + gq * 4);
    int myidx[4] = {nb4.x, nb4.y, nb4.z, nb4.w};
    const int  selfn = nodes2[grow_g];
    const float tk   = t_kernel[0];
    const float dec  = __expf(-tk * (t2[grow_g] - n_times2[grow_g]));

    float acc[2][8][4];
#pragma unroll
    for (int mt = 0; mt < 2; ++mt)
#pragma unroll
        for (int nt = 0; nt < 8; ++nt)
#pragma unroll
            for (int q = 0; q < 4; ++q) acc[mt][nt][q] = 0.f;

    // ---- gather one 64x32 A chunk into registers ----
    float4 g0, g1;
    auto do_gather = [&](int k0) {
        if (k0 < 128) {
            g0 = make_float4(0.f, 0.f, 0.f, 0.f);
            g1 = make_float4(0.f, 0.f, 0.f, 0.f);
#pragma unroll
            for (int j = 0; j < KF; ++j) {
                int src = (lane & ~3) | (j >> 2);
                int idx = __shfl_sync(0xffffffffu, myidx[j & 3], src);
                const float4* p = (const float4*)(x + (long)idx * D_IN + k0 + gq * 8);
                float4 a = p[0], b = p[1];
                g0.x += a.x; g0.y += a.y; g0.z += a.z; g0.w += a.w;
                g1.x += b.x; g1.y += b.y; g1.z += b.z; g1.w += b.w;
            }
        } else {
            const float4* p = (const float4*)(x + (long)selfn * D_IN + (k0 - 128) + gq * 8);
            float4 a = p[0], b = p[1];
            g0 = make_float4(a.x * dec, a.y * dec, a.z * dec, a.w * dec);
            g1 = make_float4(b.x * dec, b.y * dec, b.z * dec, b.w * dec);
        }
    };
    auto store_A = [&](int buf) {
        float* dst = As + buf * AS1_F + grow * 36 + gq * 8;
        float4 c0 = { to_tf32(g0.x), to_tf32(g0.y), to_tf32(g0.z), to_tf32(g0.w) };
        float4 c1 = { to_tf32(g1.x), to_tf32(g1.y), to_tf32(g1.z), to_tf32(g1.w) };
        *(float4*)dst = c0;
        *(float4*)(dst + 4) = c1;
    };
    auto load_W = [&](int buf, int k0) {
        float* Wd = Ws + buf * WS1_F;
#pragma unroll
        for (int p = 0; p < 8; ++p) {
            int idx = tid + p * 256;     // 0..2047
            int n = idx >> 3;            // 0..255
            int k4 = (idx & 7) << 2;     // 0,4,...,28
            cp_async16(&Wd[n * 36 + k4], &W[(long)n * 256 + k0 + k4]);
        }
        asm volatile("cp.async.commit_group;" ::: "memory");
    };

    // prologue: A chunk 0 + W chunk 0 into buf 0
    do_gather(0);
    store_A(0);
    load_W(0, 0);

#pragma unroll
    for (int it = 0; it < 8; ++it) {
        asm volatile("cp.async.wait_group 0;" ::: "memory");
        __syncthreads();

        if (it < 7) load_W((it + 1) & 1, (it + 1) * 32);
        if (it < 7) do_gather((it + 1) * 32);   // LDGs overlap the MMAs below

        const float* Ab = As + (it & 1) * AS1_F;
        const float* Wb = Ws + (it & 1) * WS1_F;
#pragma unroll
        for (int ks = 0; ks < 4; ++ks) {
            const int kk = ks * 8;
            uint32_t af[2][4];
            uint32_t bf[8][2];
#pragma unroll
            for (int mt = 0; mt < 2; ++mt) {
                const int m0 = wm + mt * 16 + gid;
                af[mt][0] = __float_as_uint(Ab[m0 * 36 + kk + tig]);
                af[mt][1] = __float_as_uint(Ab[(m0 + 8) * 36 + kk + tig]);
                af[mt][2] = __float_as_uint(Ab[m0 * 36 + kk + tig + 4]);
                af[mt][3] = __float_as_uint(Ab[(m0 + 8) * 36 + kk + tig + 4]);
            }
#pragma unroll
            for (int nt = 0; nt < 8; ++nt) {
                const int n0 = wn + nt * 8 + gid;
                bf[nt][0] = __float_as_uint(Wb[n0 * 36 + kk + tig]);
                bf[nt][1] = __float_as_uint(Wb[n0 * 36 + kk + tig + 4]);
            }
#pragma unroll
            for (int mt = 0; mt < 2; ++mt)
#pragma unroll
                for (int nt = 0; nt < 8; ++nt)
                    MMA_TF32(acc[mt][nt], af[mt], bf[nt]);
        }

        if (it < 7) store_A((it + 1) & 1);      // other buffer; next read after top sync
    }

    // epilogue: bias + relu; neighbor rows -> segment sums, self rows -> h1s
    const bool selfRows = (bm >= E1);
#pragma unroll
    for (int mt = 0; mt < 2; ++mt) {
#pragma unroll
        for (int nt = 0; nt < 8; ++nt) {
            const int col = wn + nt * 8 + 2 * tig;
            const float bv0 = bias[col];
            const float bv1 = bias[col + 1];
            float a0 = fmaxf(acc[mt][nt][0] + bv0, 0.f);
            float a1 = fmaxf(acc[mt][nt][1] + bv1, 0.f);
            float a2 = fmaxf(acc[mt][nt][2] + bv0, 0.f);
            float a3 = fmaxf(acc[mt][nt][3] + bv1, 0.f);
            if (selfRows) {
                const long r0 = bm + wm + mt * 16 + gid - E1;
                float2 v0 = {a0, a1}, v1 = {a2, a3};
                *(float2*)&Cself[r0 * 256 + col] = v0;
                *(float2*)&Cself[(r0 + 8) * 256 + col] = v1;
            } else {
                float s0 = a0 + a2;
                float s1 = a1 + a3;
                s0 += __shfl_xor_sync(0xffffffffu, s0, 4);
                s1 += __shfl_xor_sync(0xffffffffu, s1, 4);
                s0 += __shfl_xor_sync(0xffffffffu, s0, 8);
                s1 += __shfl_xor_sync(0xffffffffu, s1, 8);
                s0 += __shfl_xor_sync(0xffffffffu, s0, 16);
                s1 += __shfl_xor_sync(0xffffffffu, s1, 16);
                if (gid == 0) {
                    const long seg = ((bm + wm) >> 4) + mt;
                    float2 v = {s0, s1};
                    *(float2*)&Agg[seg * 256 + col] = v;
                }
            }
        }
    }
}

// ---------------------------------------------------------------------------
// Kernel 3: gemm2 — Bcat tile from [agg1 | h1s*decay], tf32 MMA vs W2,
// K-chunk 64, 3-stage cp.async ring. (unchanged from R14 — measured good)
// ---------------------------------------------------------------------------
#define AS2_STRIDE 516
#define AS2_F      (16 * AS2_STRIDE)   // 8256 floats
#define WS2_STRIDE 68
#define WS2_F      (128 * WS2_STRIDE)  // 8704 floats per stage

__global__ __launch_bounds__(256) void gemm2_fused(const float* __restrict__ ts,
                                                   const float* __restrict__ n_times1,
                                                   const float* __restrict__ t_kernel,
                                                   float* __restrict__ out) {
    extern __shared__ float sm2[];      // As[16][516] | Ws[3][128][68]
    float* As = sm2;
    float* Ws = sm2 + AS2_F;

    const int bm   = blockIdx.x * 16;
    const int tid  = threadIdx.x;
    const int lane = tid & 31;
    const int warp = tid >> 5;          // 0..7
    const int gid  = lane >> 2;         // 0..7
    const int tig  = lane & 3;          // 0..3
    const float tk = t_kernel[0];

#pragma unroll
    for (int p = 0; p < 8; ++p) {
        int idx = tid + p * 256;        // 0..2047
        int r = idx >> 7;               // 0..15
        int c = idx & 127;              // float4 col 0..127
        int b = bm + r;
        float4 v;
        if (c < 64) {
            v = ((const float4*)(g_agg1 + (long)b * 256))[c];
        } else {
            float dec = __expf(-tk * (ts[b] - n_times1[b]));
            float4 t = ((const float4*)(g_h1s + (long)b * 256))[c - 64];
            v.x = t.x * dec; v.y = t.y * dec; v.z = t.z * dec; v.w = t.w * dec;
        }
        float4 o = { to_tf32(v.x), to_tf32(v.y), to_tf32(v.z), to_tf32(v.w) };
        *(float4*)&As[r * AS2_STRIDE + c * 4] = o;
    }

#pragma unroll
    for (int s = 0; s < 2; ++s) {
        float* Wd = Ws + s * WS2_F;
        const int k0 = s * 64;
#pragma unroll
        for (int p = 0; p < 8; ++p) {
            int idx = tid + p * 256;    // 0..2047
            int n = idx >> 4;           // 0..127
            int k4 = (idx & 15) << 2;   // 0,4,...,60
            cp_async16(&Wd[n * WS2_STRIDE + k4], &g_W2[(long)n * 512 + k0 + k4]);
        }
        asm volatile("cp.async.commit_group;" ::: "memory");
    }

    float acc[2][4];
#pragma unroll
    for (int nt = 0; nt < 2; ++nt)
#pragma unroll
        for (int q = 0; q < 4; ++q) acc[nt][q] = 0.f;

#pragma unroll
    for (int ch = 0; ch < 8; ++ch) {
        if (ch < 7)
            asm volatile("cp.async.wait_group 1;" ::: "memory");
        else
            asm volatile("cp.async.wait_group 0;" ::: "memory");
        __syncthreads();

        if (ch + 2 < 8) {
            float* Wd = Ws + ((ch + 2) % 3) * WS2_F;
            const int k0 = (ch + 2) * 64;
#pragma unroll
            for (int p = 0; p < 8; ++p) {
                int idx = tid + p * 256;
                int n = idx >> 4;
                int k4 = (idx & 15) << 2;
                cp_async16(&Wd[n * WS2_STRIDE + k4], &g_W2[(long)n * 512 + k0 + k4]);
            }
            asm volatile("cp.async.commit_group;" ::: "memory");
        }

        const float* Wb = Ws + (ch % 3) * WS2_F;
#pragma unroll
        for (int ks = 0; ks < 8; ++ks) {
            const int ka = ch * 64 + ks * 8;
            const int kw = ks * 8;
            uint32_t af[4];
            af[0] = __float_as_uint(As[gid * AS2_STRIDE + ka + tig]);
            af[1] = __float_as_uint(As[(gid + 8) * AS2_STRIDE + ka + tig]);
            af[2] = __float_as_uint(As[gid * AS2_STRIDE + ka + tig + 4]);
            af[3] = __float_as_uint(As[(gid + 8) * AS2_STRIDE + ka + tig + 4]);
#pragma unroll
            for (int nt = 0; nt < 2; ++nt) {
                const int n0 = warp * 16 + nt * 8 + gid;
                uint32_t bf[2];
                bf[0] = __float_as_uint(Wb[n0 * WS2_STRIDE + kw + tig]);
                bf[1] = __float_as_uint(Wb[n0 * WS2_STRIDE + kw + tig + 4]);
                MMA_TF32(acc[nt], af, bf);
            }
        }
    }

#pragma unroll
    for (int nt = 0; nt < 2; ++nt) {
        const int col = warp * 16 + nt * 8 + 2 * tig;
        const float bv0 = g_b2[col];
        const float bv1 = g_b2[col + 1];
        float2 v0, v1;
        v0.x = acc[nt][0] + bv0; v0.x = v0.x > 0.f ? v0.x : 0.f;
        v0.y = acc[nt][1] + bv1; v0.y = v0.y > 0.f ? v0.y : 0.f;
        v1.x = acc[nt][2] + bv0; v1.x = v1.x > 0.f ? v1.x : 0.f;
        v1.y = acc[nt][3] + bv1; v1.y = v1.y > 0.f ? v1.y : 0.f;
        *(float2*)&out[(long)(bm + gid) * OUTD + col] = v0;
        *(float2*)&out[(long)(bm + gid + 8) * OUTD + col] = v1;
    }
}

// ---------------------------------------------------------------------------
// Launch
// ---------------------------------------------------------------------------
extern "C" void kernel_launch(void* const* d_in, const int* in_sizes, int n_in,
                              void* d_out, int out_size) {
    const float* x        = (const float*)d_in[0];
    const float* ts       = (const float*)d_in[1];
    const float* t2       = (const float*)d_in[2];
    const float* n_times1 = (const float*)d_in[3];
    const float* n_times2 = (const float*)d_in[4];
    const float* W1n      = (const float*)d_in[5];
    const float* b1n      = (const float*)d_in[6];
    const float* W1h      = (const float*)d_in[7];
    const float* b1h      = (const float*)d_in[8];
    const float* W2n      = (const float*)d_in[9];
    const float* b2n      = (const float*)d_in[10];
    const float* W2h      = (const float*)d_in[11];
    const float* b2h      = (const float*)d_in[12];
    const float* t_kernel = (const float*)d_in[13];
    const int*   nodes2   = (const int*)d_in[14];
    const int*   nbr2     = (const int*)d_in[15];
    float* out = (float*)d_out;

    float *pW1, *pb1, *pH1s, *pAgg;
    cudaGetSymbolAddress((void**)&pW1, g_W1);
    cudaGetSymbolAddress((void**)&pb1, g_b1);
    cudaGetSymbolAddress((void**)&pH1s, g_h1s);
    cudaGetSymbolAddress((void**)&pAgg, g_agg1);

    const int smem1 = 2 * (AS1_F + WS1_F) * sizeof(float);         // 92160 B
    cudaFuncSetAttribute(gemm1_fused, cudaFuncAttributeMaxDynamicSharedMemorySize, smem1);
    const int smem2 = (AS2_F + 3 * WS2_F) * sizeof(float);         // 137472 B
    cudaFuncSetAttribute(gemm2_fused, cudaFuncAttributeMaxDynamicSharedMemorySize, smem2);

    prep_w<<<HID, 512>>>(W1n, b1n, W1h, b1h, W2n, b2n, W2h, b2h);

    gemm1_fused<<<N2 / 64, 256, smem1>>>(x, nodes2, nbr2, t2, n_times2, t_kernel,
                                         pW1, pb1, pH1s, pAgg);

    gemm2_fused<<<BATCH / 16, 256, smem2>>>(ts, n_times1, t_kernel, out);
}

// round 16
// speedup vs baseline: 1.1130x; 1.1130x over previous
#include <cuda_runtime.h>
#include <cuda_bf16.h>
#include <cstdint>

// Problem constants (fixed by setup_inputs)
#define NN    200000
#define D_IN  128
#define HID   256
#define OUTD  128
#define BATCH 2048
#define KF    16
#define N2    (BATCH*KF + BATCH)   // 34816
#define E1    (BATCH*KF)           // 32768

// Scratch (device globals; no runtime allocation allowed)
__device__ float g_Acat[N2 * 2 * D_IN];     // [N2, 256] = [agg2 | hn1] (tf32-rounded)
__device__ float g_h1s[BATCH * HID];        // [2048, 256] self rows of h1
__device__ float g_agg1[BATCH * HID];       // [2048, 256] segment sums of h1
__device__ float g_W1[HID * 2 * D_IN];      // [256, 256] = [W1n | W1h] (tf32-rounded)
__device__ float g_b1[HID];
__device__ float g_W2[OUTD * 2 * HID];      // [128, 512] = [W2n | W2h] (tf32-rounded)
__device__ float g_b2[OUTD];

__device__ __forceinline__ float to_tf32(float f) {
    uint32_t u;
    asm("cvt.rna.tf32.f32 %0, %1;" : "=r"(u) : "f"(f));
    return __uint_as_float(u);
}

// ---------------------------------------------------------------------------
// Kernel 1: weight prep (blocks < 256) + build Acat.
// TWO rows per warp, interleaved accumulators -> 2x memory-level parallelism.
// grid = N2/16 = 2176 blocks, 256 threads (8 warps x 2 rows).
// ---------------------------------------------------------------------------
__global__ __launch_bounds__(256) void build_acat(const float* __restrict__ x,
                           const int*   __restrict__ nodes2,
                           const int*   __restrict__ nbr2,
                           const float* __restrict__ t2,
                           const float* __restrict__ n_times2,
                           const float* __restrict__ t_kernel,
                           const float* __restrict__ W1n, const float* __restrict__ b1n,
                           const float* __restrict__ W1h, const float* __restrict__ b1h,
                           const float* __restrict__ W2n, const float* __restrict__ b2n,
                           const float* __restrict__ W2h, const float* __restrict__ b2h) {
    // ---- folded weight prep (consumed only by later kernels; no sync needed)
    if (blockIdx.x < HID) {
        const int b = blockIdx.x;
        const int k = threadIdx.x;
        float w = (k < D_IN) ? W1n[b * D_IN + k] : W1h[b * D_IN + (k - D_IN)];
        g_W1[b * 256 + k] = to_tf32(w);
        if (k == 0) g_b1[b] = b1n[b] + b1h[b];
        if (b < OUTD) {
#pragma unroll
            for (int kk = k; kk < 512; kk += 256) {
                float w2 = (kk < HID) ? W2n[b * HID + kk] : W2h[b * HID + (kk - HID)];
                g_W2[b * 512 + kk] = to_tf32(w2);
            }
            if (k == 0) g_b2[b] = b2n[b] + b2h[b];
        }
    }

    const int warp = threadIdx.x >> 5;
    const int lane = threadIdx.x & 31;
    const long i0 = (long)blockIdx.x * 16 + warp * 2;   // rows i0, i0+1
    const float tk = t_kernel[0];

    // lanes 0..15 carry row i0's 16 neighbor indices, lanes 16..31 row i0+1's
    int nbj = nbr2[(i0 + (lane >> 4)) * KF + (lane & 15)];

    float4 s0 = make_float4(0.f, 0.f, 0.f, 0.f);
    float4 s1 = make_float4(0.f, 0.f, 0.f, 0.f);
#pragma unroll
    for (int j = 0; j < KF; ++j) {
        int ia = __shfl_sync(0xffffffffu, nbj, j);        // row i0, neighbor j
        int ib = __shfl_sync(0xffffffffu, nbj, 16 + j);   // row i0+1, neighbor j
        float4 va = ((const float4*)(x + (long)ia * D_IN))[lane];
        float4 vb = ((const float4*)(x + (long)ib * D_IN))[lane];
        s0.x += va.x; s0.y += va.y; s0.z += va.z; s0.w += va.w;
        s1.x += vb.x; s1.y += vb.y; s1.z += vb.z; s1.w += vb.w;
    }
    float4 o0 = { to_tf32(s0.x), to_tf32(s0.y), to_tf32(s0.z), to_tf32(s0.w) };
    float4 o1 = { to_tf32(s1.x), to_tf32(s1.y), to_tf32(s1.z), to_tf32(s1.w) };
    ((float4*)(g_Acat + i0 * 256))[lane] = o0;
    ((float4*)(g_Acat + (i0 + 1) * 256))[lane] = o1;

    // self halves (two rows, interleaved loads)
    float dec0 = __expf(-tk * (t2[i0] - n_times2[i0]));
    float dec1 = __expf(-tk * (t2[i0 + 1] - n_times2[i0 + 1]));
    float4 h0 = ((const float4*)(x + (long)nodes2[i0] * D_IN))[lane];
    float4 h1 = ((const float4*)(x + (long)nodes2[i0 + 1] * D_IN))[lane];
    float4 ho0 = { to_tf32(h0.x * dec0), to_tf32(h0.y * dec0), to_tf32(h0.z * dec0), to_tf32(h0.w * dec0) };
    float4 ho1 = { to_tf32(h1.x * dec1), to_tf32(h1.y * dec1), to_tf32(h1.z * dec1), to_tf32(h1.w * dec1) };
    ((float4*)(g_Acat + i0 * 256 + 128))[lane] = ho0;
    ((float4*)(g_Acat + (i0 + 1) * 256 + 128))[lane] = ho1;
}

// ---------------------------------------------------------------------------
// Kernel 2: tf32 tensor-core GEMM-NT + bias + relu, 3-stage cp.async pipeline.
// Epilogue: neighbor rows (bm < E1) -> in-register 16-row segment sums into
// g_agg1; self rows (bm >= E1) -> g_h1s. (unchanged — measured good)
// ---------------------------------------------------------------------------
#define MMA_TF32(d, a, b)                                                     \
    asm volatile(                                                             \
        "mma.sync.aligned.m16n8k8.row.col.f32.tf32.tf32.f32 "                 \
        "{%0,%1,%2,%3}, {%4,%5,%6,%7}, {%8,%9}, {%0,%1,%2,%3};"               \
        : "+f"((d)[0]), "+f"((d)[1]), "+f"((d)[2]), "+f"((d)[3])              \
        : "r"((a)[0]), "r"((a)[1]), "r"((a)[2]), "r"((a)[3]),                 \
          "r"((b)[0]), "r"((b)[1]))

__device__ __forceinline__ void cp_async16(void* smem_ptr, const void* gptr) {
    uint32_t sa = (uint32_t)__cvta_generic_to_shared(smem_ptr);
    asm volatile("cp.async.cg.shared.global [%0], [%1], 16;" :: "r"(sa), "l"(gptr) : "memory");
}

#define TILE_F  (128 * 36)        // floats per operand per stage
#define STAGE_F (2 * TILE_F)      // floats per stage (As + Ws)

__global__ __launch_bounds__(256, 2) void gemm1_tf32(const float* __restrict__ A,
                                                     const float* __restrict__ W,
                                                     const float* __restrict__ bias,
                                                     float* __restrict__ Cself,
                                                     float* __restrict__ Agg) {
    extern __shared__ float smem[];   // [3][ As 128*36 | Ws 128*36 ]

    const int tid  = threadIdx.x;
    const int lane = tid & 31;
    const int warp = tid >> 5;
    const int gid  = lane >> 2;     // 0..7
    const int tig  = lane & 3;      // 0..3
    const int wm   = (warp >> 2) << 6;   // 0 / 64
    const int wn   = (warp & 3) << 5;    // 0,32,64,96
    const long bm  = (long)blockIdx.y * 128;
    const int  bn  = blockIdx.x * 128;

    const int lr = tid >> 3;         // 0..31, +32 per chunk
    const int lc = (tid & 7) << 2;   // 0,4,...,28

    float acc[4][4][4];
#pragma unroll
    for (int mt = 0; mt < 4; ++mt)
#pragma unroll
        for (int nt = 0; nt < 4; ++nt)
#pragma unroll
            for (int q = 0; q < 4; ++q) acc[mt][nt][q] = 0.f;

    // prologue: stage 0 and 1
#pragma unroll
    for (int s = 0; s < 2; ++s) {
        float* Ad = smem + s * STAGE_F;
        float* Wd = Ad + TILE_F;
        const int k0 = s * 32;
#pragma unroll
        for (int p = 0; p < 4; ++p) {
            int row = lr + p * 32;
            cp_async16(&Ad[row * 36 + lc], &A[(bm + row) * 256 + k0 + lc]);
            cp_async16(&Wd[row * 36 + lc], &W[(long)(bn + row) * 256 + k0 + lc]);
        }
        asm volatile("cp.async.commit_group;" ::: "memory");
    }

#pragma unroll
    for (int it = 0; it < 8; ++it) {
        if (it < 7)
            asm volatile("cp.async.wait_group 1;" ::: "memory");
        else
            asm volatile("cp.async.wait_group 0;" ::: "memory");
        __syncthreads();

        if (it + 2 < 8) {
            const int s = (it + 2) % 3;
            float* Ad = smem + s * STAGE_F;
            float* Wd = Ad + TILE_F;
            const int k0 = (it + 2) * 32;
#pragma unroll
            for (int p = 0; p < 4; ++p) {
                int row = lr + p * 32;
                cp_async16(&Ad[row * 36 + lc], &A[(bm + row) * 256 + k0 + lc]);
                cp_async16(&Wd[row * 36 + lc], &W[(long)(bn + row) * 256 + k0 + lc]);
            }
            asm volatile("cp.async.commit_group;" ::: "memory");
        }

        const float* Ab = smem + (it % 3) * STAGE_F;
        const float* Wb = Ab + TILE_F;
#pragma unroll
        for (int ks = 0; ks < 4; ++ks) {
            const int kk = ks * 8;
            uint32_t af[4][4];
            uint32_t bf[4][2];
#pragma unroll
            for (int mt = 0; mt < 4; ++mt) {
                const int m0 = wm + mt * 16 + gid;
                af[mt][0] = __float_as_uint(Ab[m0 * 36 + kk + tig]);
                af[mt][1] = __float_as_uint(Ab[(m0 + 8) * 36 + kk + tig]);
                af[mt][2] = __float_as_uint(Ab[m0 * 36 + kk + tig + 4]);
                af[mt][3] = __float_as_uint(Ab[(m0 + 8) * 36 + kk + tig + 4]);
            }
#pragma unroll
            for (int nt = 0; nt < 4; ++nt) {
                const int n0 = wn + nt * 8 + gid;
                bf[nt][0] = __float_as_uint(Wb[n0 * 36 + kk + tig]);
                bf[nt][1] = __float_as_uint(Wb[n0 * 36 + kk + tig + 4]);
            }
#pragma unroll
            for (int mt = 0; mt < 4; ++mt)
#pragma unroll
                for (int nt = 0; nt < 4; ++nt)
                    MMA_TF32(acc[mt][nt], af[mt], bf[nt]);
        }
    }

    // epilogue
    const bool selfRows = (bm >= E1);
#pragma unroll
    for (int mt = 0; mt < 4; ++mt) {
#pragma unroll
        for (int nt = 0; nt < 4; ++nt) {
            const int col = bn + wn + nt * 8 + 2 * tig;
            const float bv0 = bias[col];
            const float bv1 = bias[col + 1];
            float a0 = fmaxf(acc[mt][nt][0] + bv0, 0.f);
            float a1 = fmaxf(acc[mt][nt][1] + bv1, 0.f);
            float a2 = fmaxf(acc[mt][nt][2] + bv0, 0.f);
            float a3 = fmaxf(acc[mt][nt][3] + bv1, 0.f);
            if (selfRows) {
                const long r0 = bm + wm + mt * 16 + gid - E1;
                float2 v0 = {a0, a1}, v1 = {a2, a3};
                *(float2*)&Cself[r0 * 256 + col] = v0;
                *(float2*)&Cself[(r0 + 8) * 256 + col] = v1;
            } else {
                // segment = 16 consecutive rows = this warp's mt-th row group
                float s0 = a0 + a2;
                float s1 = a1 + a3;
                s0 += __shfl_xor_sync(0xffffffffu, s0, 4);
                s1 += __shfl_xor_sync(0xffffffffu, s1, 4);
                s0 += __shfl_xor_sync(0xffffffffu, s0, 8);
                s1 += __shfl_xor_sync(0xffffffffu, s1, 8);
                s0 += __shfl_xor_sync(0xffffffffu, s0, 16);
                s1 += __shfl_xor_sync(0xffffffffu, s1, 16);
                if (gid == 0) {
                    const long seg = ((bm + wm) >> 4) + mt;
                    float2 v = {s0, s1};
                    *(float2*)&Agg[seg * 256 + col] = v;
                }
            }
        }
    }
}

// ---------------------------------------------------------------------------
// Kernel 3: gemm2 — Bcat tile from [agg1 | h1s*decay], tf32 MMA vs W2,
// K-chunk 64, 3-stage cp.async ring. (unchanged — measured good)
// ---------------------------------------------------------------------------
#define AS2_STRIDE 516
#define AS2_F      (16 * AS2_STRIDE)   // 8256 floats
#define WS2_STRIDE 68
#define WS2_F      (128 * WS2_STRIDE)  // 8704 floats per stage

__global__ __launch_bounds__(256) void gemm2_fused(const float* __restrict__ ts,
                                                   const float* __restrict__ n_times1,
                                                   const float* __restrict__ t_kernel,
                                                   float* __restrict__ out) {
    extern __shared__ float sm2[];      // As[16][516] | Ws[3][128][68]
    float* As = sm2;
    float* Ws = sm2 + AS2_F;

    const int bm   = blockIdx.x * 16;
    const int tid  = threadIdx.x;
    const int lane = tid & 31;
    const int warp = tid >> 5;          // 0..7
    const int gid  = lane >> 2;         // 0..7
    const int tig  = lane & 3;          // 0..3
    const float tk = t_kernel[0];

#pragma unroll
    for (int p = 0; p < 8; ++p) {
        int idx = tid + p * 256;        // 0..2047
        int r = idx >> 7;               // 0..15
        int c = idx & 127;              // float4 col 0..127
        int b = bm + r;
        float4 v;
        if (c < 64) {
            v = ((const float4*)(g_agg1 + (long)b * 256))[c];
        } else {
            float dec = __expf(-tk * (ts[b] - n_times1[b]));
            float4 t = ((const float4*)(g_h1s + (long)b * 256))[c - 64];
            v.x = t.x * dec; v.y = t.y * dec; v.z = t.z * dec; v.w = t.w * dec;
        }
        float4 o = { to_tf32(v.x), to_tf32(v.y), to_tf32(v.z), to_tf32(v.w) };
        *(float4*)&As[r * AS2_STRIDE + c * 4] = o;
    }

#pragma unroll
    for (int s = 0; s < 2; ++s) {
        float* Wd = Ws + s * WS2_F;
        const int k0 = s * 64;
#pragma unroll
        for (int p = 0; p < 8; ++p) {
            int idx = tid + p * 256;    // 0..2047
            int n = idx >> 4;           // 0..127
            int k4 = (idx & 15) << 2;   // 0,4,...,60
            cp_async16(&Wd[n * WS2_STRIDE + k4], &g_W2[(long)n * 512 + k0 + k4]);
        }
        asm volatile("cp.async.commit_group;" ::: "memory");
    }

    float acc[2][4];
#pragma unroll
    for (int nt = 0; nt < 2; ++nt)
#pragma unroll
        for (int q = 0; q < 4; ++q) acc[nt][q] = 0.f;

#pragma unroll
    for (int ch = 0; ch < 8; ++ch) {
        if (ch < 7)
            asm volatile("cp.async.wait_group 1;" ::: "memory");
        else
            asm volatile("cp.async.wait_group 0;" ::: "memory");
        __syncthreads();

        if (ch + 2 < 8) {
            float* Wd = Ws + ((ch + 2) % 3) * WS2_F;
            const int k0 = (ch + 2) * 64;
#pragma unroll
            for (int p = 0; p < 8; ++p) {
                int idx = tid + p * 256;
                int n = idx >> 4;
                int k4 = (idx & 15) << 2;
                cp_async16(&Wd[n * WS2_STRIDE + k4], &g_W2[(long)n * 512 + k0 + k4]);
            }
            asm volatile("cp.async.commit_group;" ::: "memory");
        }

        const float* Wb = Ws + (ch % 3) * WS2_F;
#pragma unroll
        for (int ks = 0; ks < 8; ++ks) {
            const int ka = ch * 64 + ks * 8;
            const int kw = ks * 8;
            uint32_t af[4];
            af[0] = __float_as_uint(As[gid * AS2_STRIDE + ka + tig]);
            af[1] = __float_as_uint(As[(gid + 8) * AS2_STRIDE + ka + tig]);
            af[2] = __float_as_uint(As[gid * AS2_STRIDE + ka + tig + 4]);
            af[3] = __float_as_uint(As[(gid + 8) * AS2_STRIDE + ka + tig + 4]);
#pragma unroll
            for (int nt = 0; nt < 2; ++nt) {
                const int n0 = warp * 16 + nt * 8 + gid;
                uint32_t bf[2];
                bf[0] = __float_as_uint(Wb[n0 * WS2_STRIDE + kw + tig]);
                bf[1] = __float_as_uint(Wb[n0 * WS2_STRIDE + kw + tig + 4]);
                MMA_TF32(acc[nt], af, bf);
            }
        }
    }

#pragma unroll
    for (int nt = 0; nt < 2; ++nt) {
        const int col = warp * 16 + nt * 8 + 2 * tig;
        const float bv0 = g_b2[col];
        const float bv1 = g_b2[col + 1];
        float2 v0, v1;
        v0.x = acc[nt][0] + bv0; v0.x = v0.x > 0.f ? v0.x : 0.f;
        v0.y = acc[nt][1] + bv1; v0.y = v0.y > 0.f ? v0.y : 0.f;
        v1.x = acc[nt][2] + bv0; v1.x = v1.x > 0.f ? v1.x : 0.f;
        v1.y = acc[nt][3] + bv1; v1.y = v1.y > 0.f ? v1.y : 0.f;
        *(float2*)&out[(long)(bm + gid) * OUTD + col] = v0;
        *(float2*)&out[(long)(bm + gid + 8) * OUTD + col] = v1;
    }
}

// ---------------------------------------------------------------------------
// Launch
// ---------------------------------------------------------------------------
extern "C" void kernel_launch(void* const* d_in, const int* in_sizes, int n_in,
                              void* d_out, int out_size) {
    const float* x        = (const float*)d_in[0];
    const float* ts       = (const float*)d_in[1];
    const float* t2       = (const float*)d_in[2];
    const float* n_times1 = (const float*)d_in[3];
    const float* n_times2 = (const float*)d_in[4];
    const float* W1n      = (const float*)d_in[5];
    const float* b1n      = (const float*)d_in[6];
    const float* W1h      = (const float*)d_in[7];
    const float* b1h      = (const float*)d_in[8];
    const float* W2n      = (const float*)d_in[9];
    const float* b2n      = (const float*)d_in[10];
    const float* W2h      = (const float*)d_in[11];
    const float* b2h      = (const float*)d_in[12];
    const float* t_kernel = (const float*)d_in[13];
    const int*   nodes2   = (const int*)d_in[14];
    const int*   nbr2     = (const int*)d_in[15];
    float* out = (float*)d_out;

    float *pAcat, *pW1, *pb1, *pH1s, *pAgg;
    cudaGetSymbolAddress((void**)&pAcat, g_Acat);
    cudaGetSymbolAddress((void**)&pW1, g_W1);
    cudaGetSymbolAddress((void**)&pb1, g_b1);
    cudaGetSymbolAddress((void**)&pH1s, g_h1s);
    cudaGetSymbolAddress((void**)&pAgg, g_agg1);

    const int smem1 = 3 * STAGE_F * sizeof(float);                 // 110592 B
    cudaFuncSetAttribute(gemm1_tf32, cudaFuncAttributeMaxDynamicSharedMemorySize, smem1);
    const int smem2 = (AS2_F + 3 * WS2_F) * sizeof(float);         // 137472 B
    cudaFuncSetAttribute(gemm2_fused, cudaFuncAttributeMaxDynamicSharedMemorySize, smem2);

    build_acat<<<N2 / 16, 256>>>(x, nodes2, nbr2, t2, n_times2, t_kernel,
                                 W1n, b1n, W1h, b1h, W2n, b2n, W2h, b2h);

    dim3 g1(2, N2 / 128);   // (2, 272)
    gemm1_tf32<<<g1, 256, smem1>>>(pAcat, pW1, pb1, pH1s, pAgg);

    gemm2_fused<<<BATCH / 16, 256, smem2>>>(ts, n_times1, t_kernel, out);
}